// round 1
// baseline (speedup 1.0000x reference)
#include <cuda_runtime.h>
#include <cuda_bf16.h>

#define N_NODES 8192
#define N_EDGES 65536
#define D_IN    768
#define D_HID   768
#define H1      8
#define D1      (H1 * D_HID)   // 6144

// ---------------- scratch (static device globals; no runtime allocation) ----
__device__ float g_h1[(size_t)N_NODES * D1];     // 201 MB  x@W1
__device__ float g_out1[(size_t)N_NODES * D1];   // 201 MB  layer-1 output (post ELU)
__device__ float g_h2[(size_t)N_NODES * D_HID];  // 25 MB   out1@W2
__device__ float g_as1[N_NODES * H1];
__device__ float g_ad1[N_NODES * H1];
__device__ float g_aE1[(size_t)N_EDGES * H1];
__device__ float g_as2[N_NODES];
__device__ float g_ad2[N_NODES];
__device__ float g_aE2[N_EDGES];
__device__ int   g_cnt[N_NODES];
__device__ int   g_indptr[N_NODES + 1];
__device__ int   g_cur[N_NODES];
__device__ int   g_eord[N_EDGES];

// ---------------- CSR build ------------------------------------------------
__global__ void k_zero_cnt() {
    int i = blockIdx.x * blockDim.x + threadIdx.x;
    if (i < N_NODES) g_cnt[i] = 0;
}

__global__ void k_count(const int* __restrict__ dst) {
    int e = blockIdx.x * blockDim.x + threadIdx.x;
    if (e < N_EDGES) atomicAdd(&g_cnt[dst[e]], 1);
}

// one block, 1024 threads, 8 elements each: exclusive scan of g_cnt -> g_indptr
__global__ void k_scan() {
    __shared__ int sh[1024];
    int t = threadIdx.x;
    int base = t * 8;
    int local[8];
    int s = 0;
#pragma unroll
    for (int i = 0; i < 8; i++) { local[i] = s; s += g_cnt[base + i]; }
    sh[t] = s;
    __syncthreads();
    for (int off = 1; off < 1024; off <<= 1) {
        int v = (t >= off) ? sh[t - off] : 0;
        __syncthreads();
        sh[t] += v;
        __syncthreads();
    }
    int prefix = (t == 0) ? 0 : sh[t - 1];
#pragma unroll
    for (int i = 0; i < 8; i++) {
        int v = prefix + local[i];
        g_indptr[base + i] = v;
        g_cur[base + i] = v;
    }
    if (t == 1023) g_indptr[N_NODES] = sh[1023];
}

__global__ void k_scatter(const int* __restrict__ dst) {
    int e = blockIdx.x * blockDim.x + threadIdx.x;
    if (e < N_EDGES) {
        int d = dst[e];
        int p = atomicAdd(&g_cur[d], 1);
        g_eord[p] = e;
    }
}

// ---------------- SGEMM: C[M,N] = A[M,K] @ B[K,N], all row-major fp32 -------
// BM=BN=128, BK=8, 256 threads, 8x8 per-thread register tile.
// Requires: M%128==0, N%128==0, K%8==0 (true for all calls here).
__global__ __launch_bounds__(256) void k_sgemm(const float* __restrict__ A,
                                               const float* __restrict__ B,
                                               float* __restrict__ C,
                                               int M, int N, int K) {
    __shared__ float As[8][128];
    __shared__ float Bs[8][128];

    int tid = threadIdx.x;
    int bm = blockIdx.y * 128;
    int bn = blockIdx.x * 128;

    int aRow = tid >> 1;           // 0..127
    int aCol = (tid & 1) * 4;      // 0 or 4
    int bRow = tid >> 5;           // 0..7
    int bCol = (tid & 31) * 4;     // 0..124

    int ty = tid >> 4;             // 0..15
    int tx = tid & 15;             // 0..15

    float acc[8][8];
#pragma unroll
    for (int i = 0; i < 8; i++)
#pragma unroll
        for (int j = 0; j < 8; j++) acc[i][j] = 0.f;

    const float* Aptr = A + (size_t)(bm + aRow) * K + aCol;
    const float* Bptr = B + (size_t)bRow * N + bn + bCol;

    for (int kt = 0; kt < K; kt += 8) {
        float4 av = *(const float4*)(Aptr + kt);
        float4 bv = *(const float4*)(Bptr + (size_t)kt * N);
        As[aCol + 0][aRow] = av.x;
        As[aCol + 1][aRow] = av.y;
        As[aCol + 2][aRow] = av.z;
        As[aCol + 3][aRow] = av.w;
        *(float4*)&Bs[bRow][bCol] = bv;
        __syncthreads();

#pragma unroll
        for (int k = 0; k < 8; k++) {
            float ar[8], br[8];
            *(float4*)(ar)     = *(const float4*)&As[k][ty * 8];
            *(float4*)(ar + 4) = *(const float4*)&As[k][ty * 8 + 4];
            *(float4*)(br)     = *(const float4*)&Bs[k][tx * 8];
            *(float4*)(br + 4) = *(const float4*)&Bs[k][tx * 8 + 4];
#pragma unroll
            for (int i = 0; i < 8; i++)
#pragma unroll
                for (int j = 0; j < 8; j++)
                    acc[i][j] += ar[i] * br[j];
        }
        __syncthreads();
    }

#pragma unroll
    for (int i = 0; i < 8; i++) {
        float* Crow = C + (size_t)(bm + ty * 8 + i) * N + bn + tx * 8;
        float4 v0 = {acc[i][0], acc[i][1], acc[i][2], acc[i][3]};
        float4 v1 = {acc[i][4], acc[i][5], acc[i][6], acc[i][7]};
        *(float4*)(Crow)     = v0;
        *(float4*)(Crow + 4) = v1;
    }
}

// ---------------- attention coefficients: per-node, warp per head -----------
// out_s[n,h] = dot(h[n,h,:], a_s[h,:]) ; out_d likewise.
__global__ void k_attn(const float* __restrict__ h,
                       const float* __restrict__ a_s,
                       const float* __restrict__ a_d,
                       float* __restrict__ out_s,
                       float* __restrict__ out_d,
                       int H) {
    int n = blockIdx.x;
    int hh = threadIdx.x >> 5;
    int lane = threadIdx.x & 31;
    const float* row = h + ((size_t)n * H + hh) * D_HID;
    const float* as = a_s + (size_t)hh * D_HID;
    const float* ad = a_d + (size_t)hh * D_HID;
    float ss = 0.f, sd = 0.f;
    for (int c = lane; c < D_HID; c += 32) {
        float v = row[c];
        ss += v * as[c];
        sd += v * ad[c];
    }
#pragma unroll
    for (int o = 16; o; o >>= 1) {
        ss += __shfl_xor_sync(0xffffffffu, ss, o);
        sd += __shfl_xor_sync(0xffffffffu, sd, o);
    }
    if (lane == 0) {
        out_s[(size_t)n * H + hh] = ss;
        out_d[(size_t)n * H + hh] = sd;
    }
}

// ---------------- segment softmax over CSR: warp per (node, head) -----------
// aE[j,h] (j = sorted edge position) = softmax over in-edges of node n.
__global__ void k_softmax(const int* __restrict__ src,
                          const float* __restrict__ as,
                          const float* __restrict__ ad,
                          float* __restrict__ aE,
                          int H) {
    int n = blockIdx.x;
    int hh = threadIdx.x >> 5;
    int lane = threadIdx.x & 31;
    int beg = g_indptr[n], end = g_indptr[n + 1];
    if (beg == end) return;
    float adn = ad[(size_t)n * H + hh];

    float m = -3.4e38f;
    for (int j = beg + lane; j < end; j += 32) {
        int s = src[g_eord[j]];
        float v = as[(size_t)s * H + hh] + adn;
        v = v > 0.f ? v : 0.2f * v;
        m = fmaxf(m, v);
    }
#pragma unroll
    for (int o = 16; o; o >>= 1) m = fmaxf(m, __shfl_xor_sync(0xffffffffu, m, o));

    float sum = 0.f;
    for (int j = beg + lane; j < end; j += 32) {
        int s = src[g_eord[j]];
        float v = as[(size_t)s * H + hh] + adn;
        v = v > 0.f ? v : 0.2f * v;
        float ex = __expf(v - m);
        aE[(size_t)j * H + hh] = ex;
        sum += ex;
    }
#pragma unroll
    for (int o = 16; o; o >>= 1) sum += __shfl_xor_sync(0xffffffffu, sum, o);

    float inv = 1.f / (sum + 1e-16f);
    for (int j = beg + lane; j < end; j += 32)
        aE[(size_t)j * H + hh] *= inv;
}

// ---------------- aggregation: block per (node, head), 256 threads ----------
// out[n,h,:] = sum_j aE[j,h] * h[src_j, h, :]  (+ bias, optional ELU)
__global__ __launch_bounds__(256) void k_aggregate(const int* __restrict__ src,
                                                   const float* __restrict__ h,
                                                   const float* __restrict__ aE,
                                                   const float* __restrict__ bias,
                                                   float* __restrict__ out,
                                                   int H, int do_elu) {
    int n = blockIdx.x;
    int hh = blockIdx.y;
    int t = threadIdx.x;
    int beg = g_indptr[n], end = g_indptr[n + 1];

    float a0 = 0.f, a1 = 0.f, a2 = 0.f;
    for (int j = beg; j < end; j++) {
        int s = src[g_eord[j]];
        float w = aE[(size_t)j * H + hh];
        const float* row = h + ((size_t)s * H + hh) * D_HID;
        a0 += row[t] * w;
        a1 += row[t + 256] * w;
        a2 += row[t + 512] * w;
    }
    const float* bb = bias + (size_t)hh * D_HID;
    float v0 = a0 + bb[t];
    float v1 = a1 + bb[t + 256];
    float v2 = a2 + bb[t + 512];
    if (do_elu) {
        v0 = v0 > 0.f ? v0 : (__expf(v0) - 1.f);
        v1 = v1 > 0.f ? v1 : (__expf(v1) - 1.f);
        v2 = v2 > 0.f ? v2 : (__expf(v2) - 1.f);
    }
    float* o = out + ((size_t)n * H + hh) * D_HID;
    o[t] = v0;
    o[t + 256] = v1;
    o[t + 512] = v2;
}

// ---------------- launch ----------------------------------------------------
extern "C" void kernel_launch(void* const* d_in, const int* in_sizes, int n_in,
                              void* d_out, int out_size) {
    const float* x      = (const float*)d_in[0];
    const float* W1     = (const float*)d_in[1];
    const float* a_src1 = (const float*)d_in[2];
    const float* a_dst1 = (const float*)d_in[3];
    const float* b1     = (const float*)d_in[4];
    const float* W2     = (const float*)d_in[5];
    const float* a_src2 = (const float*)d_in[6];
    const float* a_dst2 = (const float*)d_in[7];
    const float* b2     = (const float*)d_in[8];
    const int*   el     = (const int*)d_in[9];
    const int* srcA = el;
    const int* dstA = el + N_EDGES;
    float* out = (float*)d_out;

    float *p_h1, *p_out1, *p_h2, *p_as1, *p_ad1, *p_aE1, *p_as2, *p_ad2, *p_aE2;
    cudaGetSymbolAddress((void**)&p_h1,   g_h1);
    cudaGetSymbolAddress((void**)&p_out1, g_out1);
    cudaGetSymbolAddress((void**)&p_h2,   g_h2);
    cudaGetSymbolAddress((void**)&p_as1,  g_as1);
    cudaGetSymbolAddress((void**)&p_ad1,  g_ad1);
    cudaGetSymbolAddress((void**)&p_aE1,  g_aE1);
    cudaGetSymbolAddress((void**)&p_as2,  g_as2);
    cudaGetSymbolAddress((void**)&p_ad2,  g_ad2);
    cudaGetSymbolAddress((void**)&p_aE2,  g_aE2);

    // CSR build (shared by both layers)
    k_zero_cnt<<<N_NODES / 256, 256>>>();
    k_count<<<N_EDGES / 256, 256>>>(dstA);
    k_scan<<<1, 1024>>>();
    k_scatter<<<N_EDGES / 256, 256>>>(dstA);

    // Layer 1
    dim3 g1(D1 / 128, N_NODES / 128);
    k_sgemm<<<g1, 256>>>(x, W1, p_h1, N_NODES, D1, D_IN);
    k_attn<<<N_NODES, 32 * H1>>>(p_h1, a_src1, a_dst1, p_as1, p_ad1, H1);
    k_softmax<<<N_NODES, 32 * H1>>>(srcA, p_as1, p_ad1, p_aE1, H1);
    dim3 ga1(N_NODES, H1);
    k_aggregate<<<ga1, 256>>>(srcA, p_h1, p_aE1, b1, p_out1, H1, 1);

    // Layer 2
    dim3 g2(D_HID / 128, N_NODES / 128);
    k_sgemm<<<g2, 256>>>(p_out1, W2, p_h2, N_NODES, D_HID, D1);
    k_attn<<<N_NODES, 32>>>(p_h2, a_src2, a_dst2, p_as2, p_ad2, 1);
    k_softmax<<<N_NODES, 32>>>(srcA, p_as2, p_ad2, p_aE2, 1);
    dim3 ga2(N_NODES, 1);
    k_aggregate<<<ga2, 256>>>(srcA, p_h2, p_aE2, b2, out, 1, 0);
}

// round 2
// speedup vs baseline: 3.0336x; 3.0336x over previous
#include <cuda_runtime.h>
#include <cuda_bf16.h>
#include <cstdint>

#define N_NODES 8192
#define N_EDGES 65536
#define D_IN    768
#define D_HID   768
#define H1      8
#define D1      (H1 * D_HID)   // 6144

typedef __nv_bfloat16 bf16;

// ---------------- scratch (static device globals) ---------------------------
__device__ float g_h1[(size_t)N_NODES * D1];     // 201 MB  x@W1 (fp32)
__device__ float g_h2[(size_t)N_NODES * D_HID];  // 25 MB   out1@W2 (fp32)
__device__ bf16  g_xh[(size_t)N_NODES * D_IN];
__device__ bf16  g_xl[(size_t)N_NODES * D_IN];
__device__ bf16  g_w1h[(size_t)D_IN * D1];
__device__ bf16  g_w1l[(size_t)D_IN * D1];
__device__ bf16  g_w2h[(size_t)D1 * D_HID];
__device__ bf16  g_w2l[(size_t)D1 * D_HID];
__device__ bf16  g_o1h[(size_t)N_NODES * D1];    // 100 MB  layer-1 out hi
__device__ bf16  g_o1l[(size_t)N_NODES * D1];    // 100 MB  layer-1 out lo
__device__ float g_as1[N_NODES * H1];
__device__ float g_ad1[N_NODES * H1];
__device__ float g_aE1[(size_t)N_EDGES * H1];
__device__ float g_as2[N_NODES];
__device__ float g_ad2[N_NODES];
__device__ float g_aE2[N_EDGES];
__device__ int   g_cnt[N_NODES];
__device__ int   g_indptr[N_NODES + 1];
__device__ int   g_cur[N_NODES];
__device__ int   g_eord[N_EDGES];

// ---------------- CSR build ------------------------------------------------
__global__ void k_zero_cnt() {
    int i = blockIdx.x * blockDim.x + threadIdx.x;
    if (i < N_NODES) g_cnt[i] = 0;
}

__global__ void k_count(const int* __restrict__ dst) {
    int e = blockIdx.x * blockDim.x + threadIdx.x;
    if (e < N_EDGES) atomicAdd(&g_cnt[dst[e]], 1);
}

__global__ void k_scan() {
    __shared__ int sh[1024];
    int t = threadIdx.x;
    int base = t * 8;
    int local[8];
    int s = 0;
#pragma unroll
    for (int i = 0; i < 8; i++) { local[i] = s; s += g_cnt[base + i]; }
    sh[t] = s;
    __syncthreads();
    for (int off = 1; off < 1024; off <<= 1) {
        int v = (t >= off) ? sh[t - off] : 0;
        __syncthreads();
        sh[t] += v;
        __syncthreads();
    }
    int prefix = (t == 0) ? 0 : sh[t - 1];
#pragma unroll
    for (int i = 0; i < 8; i++) {
        int v = prefix + local[i];
        g_indptr[base + i] = v;
        g_cur[base + i] = v;
    }
    if (t == 1023) g_indptr[N_NODES] = sh[1023];
}

__global__ void k_scatter(const int* __restrict__ dst) {
    int e = blockIdx.x * blockDim.x + threadIdx.x;
    if (e < N_EDGES) {
        int d = dst[e];
        int p = atomicAdd(&g_cur[d], 1);
        g_eord[p] = e;
    }
}

// ---------------- fp32 -> bf16 hi/lo split (vectorized x4) ------------------
__global__ void k_split4(const float4* __restrict__ in,
                         uint2* __restrict__ hi, uint2* __restrict__ lo,
                         int n4) {
    int i = blockIdx.x * blockDim.x + threadIdx.x;
    if (i >= n4) return;
    float4 v = in[i];
    bf16 hx = __float2bfloat16(v.x);
    bf16 hy = __float2bfloat16(v.y);
    bf16 hz = __float2bfloat16(v.z);
    bf16 hw = __float2bfloat16(v.w);
    bf16 lx = __float2bfloat16(v.x - __bfloat162float(hx));
    bf16 ly = __float2bfloat16(v.y - __bfloat162float(hy));
    bf16 lz = __float2bfloat16(v.z - __bfloat162float(hz));
    bf16 lw = __float2bfloat16(v.w - __bfloat162float(hw));
    uint2 hv, lv;
    hv.x = ((uint32_t)__bfloat16_as_ushort(hy) << 16) | __bfloat16_as_ushort(hx);
    hv.y = ((uint32_t)__bfloat16_as_ushort(hw) << 16) | __bfloat16_as_ushort(hz);
    lv.x = ((uint32_t)__bfloat16_as_ushort(ly) << 16) | __bfloat16_as_ushort(lx);
    lv.y = ((uint32_t)__bfloat16_as_ushort(lw) << 16) | __bfloat16_as_ushort(lz);
    hi[i] = hv;
    lo[i] = lv;
}

// ---------------- tensor-core GEMM (3x bf16 split) --------------------------
// C[M,N] (fp32) = (Ah+Al)[M,K] @ (Bh+Bl)[K,N], via Ah*Bh + Ah*Bl + Al*Bh.
// BM=BN=128, BK=32, 256 threads (8 warps, 4x2), mma.m16n8k16, cp.async 2-stage.
#define A_PAD 40    // halfs per A smem row (32 data + 8 pad)
#define B_PAD 136   // halfs per B smem row (128 data + 8 pad)
#define A_HALFS (128 * A_PAD)  // 5120
#define B_HALFS (32 * B_PAD)   // 4352

#define LDSM4(R, addr) \
    asm volatile("ldmatrix.sync.aligned.m8n8.x4.shared.b16 {%0,%1,%2,%3}, [%4];" \
        : "=r"(R[0]), "=r"(R[1]), "=r"(R[2]), "=r"(R[3]) : "r"(addr))

#define LDSM4T(R0, R1, R2, R3, addr) \
    asm volatile("ldmatrix.sync.aligned.m8n8.x4.trans.shared.b16 {%0,%1,%2,%3}, [%4];" \
        : "=r"(R0), "=r"(R1), "=r"(R2), "=r"(R3) : "r"(addr))

#define MMA16816(D, A, B) \
    asm volatile("mma.sync.aligned.m16n8k16.row.col.f32.bf16.bf16.f32 " \
        "{%0,%1,%2,%3}, {%4,%5,%6,%7}, {%8,%9}, {%0,%1,%2,%3};" \
        : "+f"(D[0]), "+f"(D[1]), "+f"(D[2]), "+f"(D[3]) \
        : "r"(A[0]), "r"(A[1]), "r"(A[2]), "r"(A[3]), "r"(B[0]), "r"(B[1]))

__device__ __forceinline__ void cp16(uint32_t saddr, const void* g) {
    asm volatile("cp.async.cg.shared.global [%0], [%1], 16;" :: "r"(saddr), "l"(g));
}

__global__ __launch_bounds__(256) void k_mma_gemm(
    const bf16* __restrict__ Ah, const bf16* __restrict__ Al,
    const bf16* __restrict__ Bh, const bf16* __restrict__ Bl,
    float* __restrict__ C, int M, int N, int K) {
    extern __shared__ bf16 smem[];
    const uint32_t sbase = (uint32_t)__cvta_generic_to_shared(smem);
    // layout: sA[stage][hl][A_HALFS], then sB[stage][hl][B_HALFS]
    const uint32_t sA0 = sbase;
    const uint32_t sB0 = sbase + 4 * A_HALFS * 2;

    const int tid = threadIdx.x;
    const int lane = tid & 31;
    const int wid = tid >> 5;
    const int wm = (wid & 3) * 32;   // warp row offset in tile
    const int wn = (wid >> 2) * 64;  // warp col offset in tile
    const int bm = blockIdx.y * 128;
    const int bn = blockIdx.x * 128;

    // per-thread load coordinates (2 chunks per matrix)
    const int arow0 = tid >> 2, acol0 = (tid & 3) * 8;
    const int arow1 = (tid + 256) >> 2, acol1 = ((tid + 256) & 3) * 8;
    const int brow0 = tid >> 4, bcol0 = (tid & 15) * 8;
    const int brow1 = (tid + 256) >> 4, bcol1 = ((tid + 256) & 15) * 8;

    float c[2][8][4];
#pragma unroll
    for (int mi = 0; mi < 2; mi++)
#pragma unroll
        for (int nj = 0; nj < 8; nj++)
#pragma unroll
            for (int q = 0; q < 4; q++) c[mi][nj][q] = 0.f;

    auto load_stage = [&](int stage, int kt) {
        uint32_t aH = sA0 + (stage * 2 + 0) * A_HALFS * 2;
        uint32_t aL = sA0 + (stage * 2 + 1) * A_HALFS * 2;
        uint32_t bH = sB0 + (stage * 2 + 0) * B_HALFS * 2;
        uint32_t bL = sB0 + (stage * 2 + 1) * B_HALFS * 2;
        size_t ga0 = (size_t)(bm + arow0) * K + kt + acol0;
        size_t ga1 = (size_t)(bm + arow1) * K + kt + acol1;
        uint32_t sa0 = (arow0 * A_PAD + acol0) * 2;
        uint32_t sa1 = (arow1 * A_PAD + acol1) * 2;
        cp16(aH + sa0, Ah + ga0); cp16(aH + sa1, Ah + ga1);
        cp16(aL + sa0, Al + ga0); cp16(aL + sa1, Al + ga1);
        size_t gb0 = (size_t)(kt + brow0) * N + bn + bcol0;
        size_t gb1 = (size_t)(kt + brow1) * N + bn + bcol1;
        uint32_t sb0 = (brow0 * B_PAD + bcol0) * 2;
        uint32_t sb1 = (brow1 * B_PAD + bcol1) * 2;
        cp16(bH + sb0, Bh + gb0); cp16(bH + sb1, Bh + gb1);
        cp16(bL + sb0, Bl + gb0); cp16(bL + sb1, Bl + gb1);
        asm volatile("cp.async.commit_group;");
    };

    load_stage(0, 0);

    const int nkt = K / 32;
    for (int it = 0; it < nkt; it++) {
        int stage = it & 1;
        if (it + 1 < nkt) {
            load_stage(stage ^ 1, (it + 1) * 32);
            asm volatile("cp.async.wait_group 1;");
        } else {
            asm volatile("cp.async.wait_group 0;");
        }
        __syncthreads();

        uint32_t aH = sA0 + (stage * 2 + 0) * A_HALFS * 2;
        uint32_t aL = sA0 + (stage * 2 + 1) * A_HALFS * 2;
        uint32_t bH = sB0 + (stage * 2 + 0) * B_HALFS * 2;
        uint32_t bL = sB0 + (stage * 2 + 1) * B_HALFS * 2;

#pragma unroll
        for (int ks = 0; ks < 32; ks += 16) {
            uint32_t afh[2][4], afl[2][4];
#pragma unroll
            for (int mi = 0; mi < 2; mi++) {
                uint32_t off = ((wm + mi * 16 + (lane & 15)) * A_PAD + ks + (lane >> 4) * 8) * 2;
                LDSM4(afh[mi], aH + off);
                LDSM4(afl[mi], aL + off);
            }
            uint32_t bfh[8][2], bfl[8][2];
            int g = lane >> 3;
            int brow = ks + (lane & 7) + (g & 1) * 8;
            int bcol_base = wn + (g >> 1) * 8;
#pragma unroll
            for (int nj2 = 0; nj2 < 4; nj2++) {
                uint32_t off = (brow * B_PAD + bcol_base + nj2 * 16) * 2;
                LDSM4T(bfh[nj2 * 2][0], bfh[nj2 * 2][1],
                       bfh[nj2 * 2 + 1][0], bfh[nj2 * 2 + 1][1], bH + off);
                LDSM4T(bfl[nj2 * 2][0], bfl[nj2 * 2][1],
                       bfl[nj2 * 2 + 1][0], bfl[nj2 * 2 + 1][1], bL + off);
            }
#pragma unroll
            for (int mi = 0; mi < 2; mi++)
#pragma unroll
                for (int nj = 0; nj < 8; nj++) {
                    MMA16816(c[mi][nj], afh[mi], bfh[nj]);
                    MMA16816(c[mi][nj], afh[mi], bfl[nj]);
                    MMA16816(c[mi][nj], afl[mi], bfh[nj]);
                }
        }
        __syncthreads();
    }

    // epilogue
#pragma unroll
    for (int mi = 0; mi < 2; mi++) {
        int row0 = bm + wm + mi * 16 + (lane >> 2);
#pragma unroll
        for (int nj = 0; nj < 8; nj++) {
            int col = bn + wn + nj * 8 + (lane & 3) * 2;
            float2 v0 = {c[mi][nj][0], c[mi][nj][1]};
            float2 v1 = {c[mi][nj][2], c[mi][nj][3]};
            *(float2*)(C + (size_t)row0 * N + col) = v0;
            *(float2*)(C + (size_t)(row0 + 8) * N + col) = v1;
        }
    }
}

// ---------------- attention coefficients: per-node, warp per head -----------
__global__ void k_attn(const float* __restrict__ h,
                       const float* __restrict__ a_s,
                       const float* __restrict__ a_d,
                       float* __restrict__ out_s,
                       float* __restrict__ out_d,
                       int H) {
    int n = blockIdx.x;
    int hh = threadIdx.x >> 5;
    int lane = threadIdx.x & 31;
    const float* row = h + ((size_t)n * H + hh) * D_HID;
    const float* as = a_s + (size_t)hh * D_HID;
    const float* ad = a_d + (size_t)hh * D_HID;
    float ss = 0.f, sd = 0.f;
    for (int c = lane; c < D_HID; c += 32) {
        float v = row[c];
        ss += v * as[c];
        sd += v * ad[c];
    }
#pragma unroll
    for (int o = 16; o; o >>= 1) {
        ss += __shfl_xor_sync(0xffffffffu, ss, o);
        sd += __shfl_xor_sync(0xffffffffu, sd, o);
    }
    if (lane == 0) {
        out_s[(size_t)n * H + hh] = ss;
        out_d[(size_t)n * H + hh] = sd;
    }
}

// ---------------- segment softmax over CSR: warp per (node, head) -----------
__global__ void k_softmax(const int* __restrict__ src,
                          const float* __restrict__ as,
                          const float* __restrict__ ad,
                          float* __restrict__ aE,
                          int H) {
    int n = blockIdx.x;
    int hh = threadIdx.x >> 5;
    int lane = threadIdx.x & 31;
    int beg = g_indptr[n], end = g_indptr[n + 1];
    if (beg == end) return;
    float adn = ad[(size_t)n * H + hh];

    float m = -3.4e38f;
    for (int j = beg + lane; j < end; j += 32) {
        int s = src[g_eord[j]];
        float v = as[(size_t)s * H + hh] + adn;
        v = v > 0.f ? v : 0.2f * v;
        m = fmaxf(m, v);
    }
#pragma unroll
    for (int o = 16; o; o >>= 1) m = fmaxf(m, __shfl_xor_sync(0xffffffffu, m, o));

    float sum = 0.f;
    for (int j = beg + lane; j < end; j += 32) {
        int s = src[g_eord[j]];
        float v = as[(size_t)s * H + hh] + adn;
        v = v > 0.f ? v : 0.2f * v;
        float ex = __expf(v - m);
        aE[(size_t)j * H + hh] = ex;
        sum += ex;
    }
#pragma unroll
    for (int o = 16; o; o >>= 1) sum += __shfl_xor_sync(0xffffffffu, sum, o);

    float inv = 1.f / (sum + 1e-16f);
    for (int j = beg + lane; j < end; j += 32)
        aE[(size_t)j * H + hh] *= inv;
}

// ---------------- aggregation layer 1: writes bf16 hi/lo (ELU + bias) -------
__global__ __launch_bounds__(256) void k_aggregate_l1(const int* __restrict__ src,
                                                      const float* __restrict__ h,
                                                      const float* __restrict__ aE,
                                                      const float* __restrict__ bias,
                                                      bf16* __restrict__ oh,
                                                      bf16* __restrict__ ol) {
    int n = blockIdx.x;
    int hh = blockIdx.y;
    int t = threadIdx.x;
    int beg = g_indptr[n], end = g_indptr[n + 1];

    float a0 = 0.f, a1 = 0.f, a2 = 0.f;
    for (int j = beg; j < end; j++) {
        int s = src[g_eord[j]];
        float w = aE[(size_t)j * H1 + hh];
        const float* row = h + ((size_t)s * H1 + hh) * D_HID;
        a0 += row[t] * w;
        a1 += row[t + 256] * w;
        a2 += row[t + 512] * w;
    }
    const float* bb = bias + (size_t)hh * D_HID;
    float v0 = a0 + bb[t];
    float v1 = a1 + bb[t + 256];
    float v2 = a2 + bb[t + 512];
    v0 = v0 > 0.f ? v0 : (__expf(v0) - 1.f);
    v1 = v1 > 0.f ? v1 : (__expf(v1) - 1.f);
    v2 = v2 > 0.f ? v2 : (__expf(v2) - 1.f);
    size_t base = ((size_t)n * H1 + hh) * D_HID;
    bf16 h0 = __float2bfloat16(v0);
    bf16 h1v = __float2bfloat16(v1);
    bf16 h2v = __float2bfloat16(v2);
    oh[base + t] = h0;
    oh[base + t + 256] = h1v;
    oh[base + t + 512] = h2v;
    ol[base + t] = __float2bfloat16(v0 - __bfloat162float(h0));
    ol[base + t + 256] = __float2bfloat16(v1 - __bfloat162float(h1v));
    ol[base + t + 512] = __float2bfloat16(v2 - __bfloat162float(h2v));
}

// ---------------- aggregation layer 2: fp32 out, no ELU ---------------------
__global__ __launch_bounds__(256) void k_aggregate_l2(const int* __restrict__ src,
                                                      const float* __restrict__ h,
                                                      const float* __restrict__ aE,
                                                      const float* __restrict__ bias,
                                                      float* __restrict__ out) {
    int n = blockIdx.x;
    int t = threadIdx.x;
    int beg = g_indptr[n], end = g_indptr[n + 1];

    float a0 = 0.f, a1 = 0.f, a2 = 0.f;
    for (int j = beg; j < end; j++) {
        int s = src[g_eord[j]];
        float w = aE[j];
        const float* row = h + (size_t)s * D_HID;
        a0 += row[t] * w;
        a1 += row[t + 256] * w;
        a2 += row[t + 512] * w;
    }
    float* o = out + (size_t)n * D_HID;
    o[t] = a0 + bias[t];
    o[t + 256] = a1 + bias[t + 256];
    o[t + 512] = a2 + bias[t + 512];
}

// ---------------- launch ----------------------------------------------------
extern "C" void kernel_launch(void* const* d_in, const int* in_sizes, int n_in,
                              void* d_out, int out_size) {
    const float* x      = (const float*)d_in[0];
    const float* W1     = (const float*)d_in[1];
    const float* a_src1 = (const float*)d_in[2];
    const float* a_dst1 = (const float*)d_in[3];
    const float* b1     = (const float*)d_in[4];
    const float* W2     = (const float*)d_in[5];
    const float* a_src2 = (const float*)d_in[6];
    const float* a_dst2 = (const float*)d_in[7];
    const float* b2     = (const float*)d_in[8];
    const int*   el     = (const int*)d_in[9];
    const int* srcA = el;
    const int* dstA = el + N_EDGES;
    float* out = (float*)d_out;

    float *p_h1, *p_h2, *p_as1, *p_ad1, *p_aE1, *p_as2, *p_ad2, *p_aE2;
    bf16 *p_xh, *p_xl, *p_w1h, *p_w1l, *p_w2h, *p_w2l, *p_o1h, *p_o1l;
    cudaGetSymbolAddress((void**)&p_h1,  g_h1);
    cudaGetSymbolAddress((void**)&p_h2,  g_h2);
    cudaGetSymbolAddress((void**)&p_xh,  g_xh);
    cudaGetSymbolAddress((void**)&p_xl,  g_xl);
    cudaGetSymbolAddress((void**)&p_w1h, g_w1h);
    cudaGetSymbolAddress((void**)&p_w1l, g_w1l);
    cudaGetSymbolAddress((void**)&p_w2h, g_w2h);
    cudaGetSymbolAddress((void**)&p_w2l, g_w2l);
    cudaGetSymbolAddress((void**)&p_o1h, g_o1h);
    cudaGetSymbolAddress((void**)&p_o1l, g_o1l);
    cudaGetSymbolAddress((void**)&p_as1, g_as1);
    cudaGetSymbolAddress((void**)&p_ad1, g_ad1);
    cudaGetSymbolAddress((void**)&p_aE1, g_aE1);
    cudaGetSymbolAddress((void**)&p_as2, g_as2);
    cudaGetSymbolAddress((void**)&p_ad2, g_ad2);
    cudaGetSymbolAddress((void**)&p_aE2, g_aE2);

    static bool s_attr_done = false;
    if (!s_attr_done) {
        cudaFuncSetAttribute(k_mma_gemm, cudaFuncAttributeMaxDynamicSharedMemorySize,
                             (4 * A_HALFS + 4 * B_HALFS) * 2);
        s_attr_done = true;
    }
    const int smem_bytes = (4 * A_HALFS + 4 * B_HALFS) * 2;  // 75776

    // CSR build
    k_zero_cnt<<<N_NODES / 256, 256>>>();
    k_count<<<N_EDGES / 256, 256>>>(dstA);
    k_scan<<<1, 1024>>>();
    k_scatter<<<N_EDGES / 256, 256>>>(dstA);

    // splits
    k_split4<<<(N_NODES * D_IN / 4 + 255) / 256, 256>>>((const float4*)x, (uint2*)p_xh, (uint2*)p_xl, N_NODES * D_IN / 4);
    k_split4<<<(D_IN * D1 / 4 + 255) / 256, 256>>>((const float4*)W1, (uint2*)p_w1h, (uint2*)p_w1l, D_IN * D1 / 4);
    k_split4<<<(D1 * D_HID / 4 + 255) / 256, 256>>>((const float4*)W2, (uint2*)p_w2h, (uint2*)p_w2l, D1 * D_HID / 4);

    // Layer 1: h1 = x @ W1
    dim3 g1(D1 / 128, N_NODES / 128);
    k_mma_gemm<<<g1, 256, smem_bytes>>>(p_xh, p_xl, p_w1h, p_w1l, p_h1, N_NODES, D1, D_IN);
    k_attn<<<N_NODES, 32 * H1>>>(p_h1, a_src1, a_dst1, p_as1, p_ad1, H1);
    k_softmax<<<N_NODES, 32 * H1>>>(srcA, p_as1, p_ad1, p_aE1, H1);
    dim3 ga1(N_NODES, H1);
    k_aggregate_l1<<<ga1, 256>>>(srcA, p_h1, p_aE1, b1, p_o1h, p_o1l);

    // Layer 2: h2 = out1 @ W2
    dim3 g2(D_HID / 128, N_NODES / 128);
    k_mma_gemm<<<g2, 256, smem_bytes>>>(p_o1h, p_o1l, p_w2h, p_w2l, p_h2, N_NODES, D_HID, D1);
    k_attn<<<N_NODES, 32>>>(p_h2, a_src2, a_dst2, p_as2, p_ad2, 1);
    k_softmax<<<N_NODES, 32>>>(srcA, p_as2, p_ad2, p_aE2, 1);
    k_aggregate_l2<<<N_NODES, 256>>>(srcA, p_h2, p_aE2, b2, out);
}

// round 4
// speedup vs baseline: 4.1227x; 1.3590x over previous
#include <cuda_runtime.h>
#include <cuda_fp16.h>
#include <cstdint>

#define N_NODES 8192
#define N_EDGES 65536
#define D_IN    768
#define D_HID   768
#define H1      8
#define D1      (H1 * D_HID)   // 6144

// ---------------- scratch (static device globals) ---------------------------
__device__ float  g_h1[(size_t)N_NODES * D1];     // x@W1 (fp32)
__device__ float  g_h2[(size_t)N_NODES * D_HID];  // out1@W2 (fp32)
__device__ __half g_xf[(size_t)N_NODES * D_IN];   // fp16(x)
__device__ __half g_w1h[(size_t)D_IN * D1];       // fp16 hi of W1 [768,6144]
__device__ __half g_w1l[(size_t)D_IN * D1];       // fp16 lo of W1
__device__ __half g_w2h[(size_t)D1 * D_HID];      // fp16 hi of W2 [6144,768]
__device__ __half g_w2l[(size_t)D1 * D_HID];
__device__ __half g_o1f[(size_t)N_NODES * D1];    // fp16(out1)
__device__ float  g_as1[N_NODES * H1];
__device__ float  g_ad1[N_NODES * H1];
__device__ float  g_aE1[(size_t)N_EDGES * H1];
__device__ float  g_as2[N_NODES];
__device__ float  g_ad2[N_NODES];
__device__ float  g_aE2[N_EDGES];
__device__ int    g_cnt[N_NODES];
__device__ int    g_indptr[N_NODES + 1];
__device__ int    g_cur[N_NODES];
__device__ int    g_eord[N_EDGES];

// ---------------- CSR build ------------------------------------------------
__global__ void k_zero_cnt() {
    int i = blockIdx.x * blockDim.x + threadIdx.x;
    if (i < N_NODES) g_cnt[i] = 0;
}
__global__ void k_count(const int* __restrict__ dst) {
    int e = blockIdx.x * blockDim.x + threadIdx.x;
    if (e < N_EDGES) atomicAdd(&g_cnt[dst[e]], 1);
}
__global__ void k_scan() {
    __shared__ int sh[1024];
    int t = threadIdx.x;
    int base = t * 8;
    int local[8];
    int s = 0;
#pragma unroll
    for (int i = 0; i < 8; i++) { local[i] = s; s += g_cnt[base + i]; }
    sh[t] = s;
    __syncthreads();
    for (int off = 1; off < 1024; off <<= 1) {
        int v = (t >= off) ? sh[t - off] : 0;
        __syncthreads();
        sh[t] += v;
        __syncthreads();
    }
    int prefix = (t == 0) ? 0 : sh[t - 1];
#pragma unroll
    for (int i = 0; i < 8; i++) {
        int v = prefix + local[i];
        g_indptr[base + i] = v;
        g_cur[base + i] = v;
    }
    if (t == 1023) g_indptr[N_NODES] = sh[1023];
}
__global__ void k_scatter(const int* __restrict__ dst) {
    int e = blockIdx.x * blockDim.x + threadIdx.x;
    if (e < N_EDGES) {
        int d = dst[e];
        int p = atomicAdd(&g_cur[d], 1);
        g_eord[p] = e;
    }
}

// ---------------- fp32 -> fp16 round (x4) ------------------------------------
__global__ void k_round4(const float4* __restrict__ in, uint2* __restrict__ o, int n4) {
    int i = blockIdx.x * blockDim.x + threadIdx.x;
    if (i >= n4) return;
    float4 v = in[i];
    __half2 lo = __floats2half2_rn(v.x, v.y);
    __half2 hi = __floats2half2_rn(v.z, v.w);
    uint2 r;
    r.x = *(uint32_t*)&lo;
    r.y = *(uint32_t*)&hi;
    o[i] = r;
}

// ---------------- fp32 -> fp16 hi/lo split (x4) ------------------------------
__global__ void k_split4(const float4* __restrict__ in,
                         uint2* __restrict__ hi, uint2* __restrict__ lo, int n4) {
    int i = blockIdx.x * blockDim.x + threadIdx.x;
    if (i >= n4) return;
    float4 v = in[i];
    __half hx = __float2half_rn(v.x), hy = __float2half_rn(v.y);
    __half hz = __float2half_rn(v.z), hw = __float2half_rn(v.w);
    __half lx = __float2half_rn(v.x - __half2float(hx));
    __half ly = __float2half_rn(v.y - __half2float(hy));
    __half lz = __float2half_rn(v.z - __half2float(hz));
    __half lw = __float2half_rn(v.w - __half2float(hw));
    uint2 hv, lv;
    hv.x = ((uint32_t)__half_as_ushort(hy) << 16) | __half_as_ushort(hx);
    hv.y = ((uint32_t)__half_as_ushort(hw) << 16) | __half_as_ushort(hz);
    lv.x = ((uint32_t)__half_as_ushort(ly) << 16) | __half_as_ushort(lx);
    lv.y = ((uint32_t)__half_as_ushort(lw) << 16) | __half_as_ushort(lz);
    hi[i] = hv;
    lo[i] = lv;
}

// ---------------- tensor-core GEMM (2x fp16 product) -------------------------
// C[M,N] fp32 = Af[M,K] @ (Bh+Bl)[K,N].
// BM=BN=128, BK=32, 256 threads (8 warps 4x2), mma.m16n8k16.f16, 2-stage.
#define A_PAD 40
#define B_PAD 136
#define A_HALFS (128 * A_PAD)  // 5120
#define B_HALFS (32 * B_PAD)   // 4352
#define STG_HALFS (A_HALFS + 2 * B_HALFS)  // 13824

#define LDSM4(R, addr) \
    asm volatile("ldmatrix.sync.aligned.m8n8.x4.shared.b16 {%0,%1,%2,%3}, [%4];" \
        : "=r"(R[0]), "=r"(R[1]), "=r"(R[2]), "=r"(R[3]) : "r"(addr))

#define LDSM4T(R0, R1, R2, R3, addr) \
    asm volatile("ldmatrix.sync.aligned.m8n8.x4.trans.shared.b16 {%0,%1,%2,%3}, [%4];" \
        : "=r"(R0), "=r"(R1), "=r"(R2), "=r"(R3) : "r"(addr))

#define MMA16816(D, A, B) \
    asm volatile("mma.sync.aligned.m16n8k16.row.col.f32.f16.f16.f32 " \
        "{%0,%1,%2,%3}, {%4,%5,%6,%7}, {%8,%9}, {%0,%1,%2,%3};" \
        : "+f"(D[0]), "+f"(D[1]), "+f"(D[2]), "+f"(D[3]) \
        : "r"(A[0]), "r"(A[1]), "r"(A[2]), "r"(A[3]), "r"(B[0]), "r"(B[1]))

__device__ __forceinline__ void cp16(uint32_t saddr, const void* g) {
    asm volatile("cp.async.cg.shared.global [%0], [%1], 16;" :: "r"(saddr), "l"(g));
}

__global__ __launch_bounds__(256) void k_mma_gemm(
    const __half* __restrict__ Af,
    const __half* __restrict__ Bh, const __half* __restrict__ Bl,
    float* __restrict__ C, int M, int N, int K) {
    extern __shared__ __half smem[];
    const uint32_t sbase = (uint32_t)__cvta_generic_to_shared(smem);

    const int tid = threadIdx.x;
    const int lane = tid & 31;
    const int wid = tid >> 5;
    const int wm = (wid & 3) * 32;
    const int wn = (wid >> 2) * 64;
    const int bm = blockIdx.y * 128;
    const int bn = blockIdx.x * 128;

    const int arow0 = tid >> 2, acol0 = (tid & 3) * 8;
    const int arow1 = (tid + 256) >> 2, acol1 = ((tid + 256) & 3) * 8;
    const int brow0 = tid >> 4, bcol0 = (tid & 15) * 8;
    const int brow1 = (tid + 256) >> 4, bcol1 = ((tid + 256) & 15) * 8;

    float c[2][8][4];
#pragma unroll
    for (int mi = 0; mi < 2; mi++)
#pragma unroll
        for (int nj = 0; nj < 8; nj++)
#pragma unroll
            for (int q = 0; q < 4; q++) c[mi][nj][q] = 0.f;

    auto load_stage = [&](int stage, int kt) {
        uint32_t aF = sbase + stage * STG_HALFS * 2;
        uint32_t bH = aF + A_HALFS * 2;
        uint32_t bL = bH + B_HALFS * 2;
        size_t ga0 = (size_t)(bm + arow0) * K + kt + acol0;
        size_t ga1 = (size_t)(bm + arow1) * K + kt + acol1;
        uint32_t sa0 = (arow0 * A_PAD + acol0) * 2;
        uint32_t sa1 = (arow1 * A_PAD + acol1) * 2;
        cp16(aF + sa0, Af + ga0);
        cp16(aF + sa1, Af + ga1);
        size_t gb0 = (size_t)(kt + brow0) * N + bn + bcol0;
        size_t gb1 = (size_t)(kt + brow1) * N + bn + bcol1;
        uint32_t sb0 = (brow0 * B_PAD + bcol0) * 2;
        uint32_t sb1 = (brow1 * B_PAD + bcol1) * 2;
        cp16(bH + sb0, Bh + gb0);
        cp16(bH + sb1, Bh + gb1);
        cp16(bL + sb0, Bl + gb0);
        cp16(bL + sb1, Bl + gb1);
        asm volatile("cp.async.commit_group;");
    };

    load_stage(0, 0);

    const int nkt = K / 32;
    for (int it = 0; it < nkt; it++) {
        int stage = it & 1;
        if (it + 1 < nkt) {
            load_stage(stage ^ 1, (it + 1) * 32);
            asm volatile("cp.async.wait_group 1;");
        } else {
            asm volatile("cp.async.wait_group 0;");
        }
        __syncthreads();

        uint32_t aF = sbase + stage * STG_HALFS * 2;
        uint32_t bH = aF + A_HALFS * 2;
        uint32_t bL = bH + B_HALFS * 2;

#pragma unroll
        for (int ks = 0; ks < 32; ks += 16) {
            uint32_t af[2][4];
#pragma unroll
            for (int mi = 0; mi < 2; mi++) {
                uint32_t off = ((wm + mi * 16 + (lane & 15)) * A_PAD + ks + (lane >> 4) * 8) * 2;
                LDSM4(af[mi], aF + off);
            }
            uint32_t bfh[8][2], bfl[8][2];
            int g = lane >> 3;
            int brow = ks + (lane & 7) + (g & 1) * 8;
            int bcol_base = wn + (g >> 1) * 8;
#pragma unroll
            for (int nj2 = 0; nj2 < 4; nj2++) {
                uint32_t off = (brow * B_PAD + bcol_base + nj2 * 16) * 2;
                LDSM4T(bfh[nj2 * 2][0], bfh[nj2 * 2][1],
                       bfh[nj2 * 2 + 1][0], bfh[nj2 * 2 + 1][1], bH + off);
                LDSM4T(bfl[nj2 * 2][0], bfl[nj2 * 2][1],
                       bfl[nj2 * 2 + 1][0], bfl[nj2 * 2 + 1][1], bL + off);
            }
#pragma unroll
            for (int mi = 0; mi < 2; mi++)
#pragma unroll
                for (int nj = 0; nj < 8; nj++) {
                    MMA16816(c[mi][nj], af[mi], bfh[nj]);
                    MMA16816(c[mi][nj], af[mi], bfl[nj]);
                }
        }
        __syncthreads();
    }

#pragma unroll
    for (int mi = 0; mi < 2; mi++) {
        int row0 = bm + wm + mi * 16 + (lane >> 2);
#pragma unroll
        for (int nj = 0; nj < 8; nj++) {
            int col = bn + wn + nj * 8 + (lane & 3) * 2;
            float2 v0 = {c[mi][nj][0], c[mi][nj][1]};
            float2 v1 = {c[mi][nj][2], c[mi][nj][3]};
            *(float2*)(C + (size_t)row0 * N + col) = v0;
            *(float2*)(C + (size_t)(row0 + 8) * N + col) = v1;
        }
    }
}

// ---------------- attention coefficients ------------------------------------
__global__ void k_attn(const float* __restrict__ h,
                       const float* __restrict__ a_s,
                       const float* __restrict__ a_d,
                       float* __restrict__ out_s,
                       float* __restrict__ out_d, int H) {
    int n = blockIdx.x;
    int hh = threadIdx.x >> 5;
    int lane = threadIdx.x & 31;
    const float* row = h + ((size_t)n * H + hh) * D_HID;
    const float* as = a_s + (size_t)hh * D_HID;
    const float* ad = a_d + (size_t)hh * D_HID;
    float ss = 0.f, sd = 0.f;
    for (int c = lane; c < D_HID; c += 32) {
        float v = row[c];
        ss += v * as[c];
        sd += v * ad[c];
    }
#pragma unroll
    for (int o = 16; o; o >>= 1) {
        ss += __shfl_xor_sync(0xffffffffu, ss, o);
        sd += __shfl_xor_sync(0xffffffffu, sd, o);
    }
    if (lane == 0) {
        out_s[(size_t)n * H + hh] = ss;
        out_d[(size_t)n * H + hh] = sd;
    }
}

// ---------------- segment softmax over CSR -----------------------------------
__global__ void k_softmax(const int* __restrict__ src,
                          const float* __restrict__ as,
                          const float* __restrict__ ad,
                          float* __restrict__ aE, int H) {
    int n = blockIdx.x;
    int hh = threadIdx.x >> 5;
    int lane = threadIdx.x & 31;
    int beg = g_indptr[n], end = g_indptr[n + 1];
    if (beg == end) return;
    float adn = ad[(size_t)n * H + hh];

    float m = -3.4e38f;
    for (int j = beg + lane; j < end; j += 32) {
        int s = src[g_eord[j]];
        float v = as[(size_t)s * H + hh] + adn;
        v = v > 0.f ? v : 0.2f * v;
        m = fmaxf(m, v);
    }
#pragma unroll
    for (int o = 16; o; o >>= 1) m = fmaxf(m, __shfl_xor_sync(0xffffffffu, m, o));

    float sum = 0.f;
    for (int j = beg + lane; j < end; j += 32) {
        int s = src[g_eord[j]];
        float v = as[(size_t)s * H + hh] + adn;
        v = v > 0.f ? v : 0.2f * v;
        float ex = __expf(v - m);
        aE[(size_t)j * H + hh] = ex;
        sum += ex;
    }
#pragma unroll
    for (int o = 16; o; o >>= 1) sum += __shfl_xor_sync(0xffffffffu, sum, o);

    float inv = 1.f / (sum + 1e-16f);
    for (int j = beg + lane; j < end; j += 32)
        aE[(size_t)j * H + hh] *= inv;
}

// ---------------- aggregation layer 1: fp16 out (ELU + bias), float4 loads --
__global__ __launch_bounds__(192) void k_aggregate_l1(const int* __restrict__ src,
                                                      const float* __restrict__ h,
                                                      const float* __restrict__ aE,
                                                      const float* __restrict__ bias,
                                                      __half* __restrict__ of) {
    int n = blockIdx.x;
    int hh = blockIdx.y;
    int t = threadIdx.x;
    int beg = g_indptr[n], end = g_indptr[n + 1];

    float a0 = 0.f, a1 = 0.f, a2 = 0.f, a3 = 0.f;
    for (int j = beg; j < end; j++) {
        int s = src[g_eord[j]];
        float w = aE[(size_t)j * H1 + hh];
        const float4* row = (const float4*)(h + ((size_t)s * H1 + hh) * D_HID);
        float4 v = row[t];
        a0 += v.x * w;
        a1 += v.y * w;
        a2 += v.z * w;
        a3 += v.w * w;
    }
    const float4 bb = ((const float4*)(bias + (size_t)hh * D_HID))[t];
    float v0 = a0 + bb.x;
    float v1 = a1 + bb.y;
    float v2 = a2 + bb.z;
    float v3 = a3 + bb.w;
    v0 = v0 > 0.f ? v0 : (__expf(v0) - 1.f);
    v1 = v1 > 0.f ? v1 : (__expf(v1) - 1.f);
    v2 = v2 > 0.f ? v2 : (__expf(v2) - 1.f);
    v3 = v3 > 0.f ? v3 : (__expf(v3) - 1.f);
    __half2 lo = __floats2half2_rn(v0, v1);
    __half2 hi = __floats2half2_rn(v2, v3);
    uint2 r;
    r.x = *(uint32_t*)&lo;
    r.y = *(uint32_t*)&hi;
    ((uint2*)(of + ((size_t)n * H1 + hh) * D_HID))[t] = r;
}

// ---------------- aggregation layer 2: fp32 out, no ELU, float4 -------------
__global__ __launch_bounds__(192) void k_aggregate_l2(const int* __restrict__ src,
                                                      const float* __restrict__ h,
                                                      const float* __restrict__ aE,
                                                      const float* __restrict__ bias,
                                                      float* __restrict__ out) {
    int n = blockIdx.x;
    int t = threadIdx.x;
    int beg = g_indptr[n], end = g_indptr[n + 1];

    float a0 = 0.f, a1 = 0.f, a2 = 0.f, a3 = 0.f;
    for (int j = beg; j < end; j++) {
        int s = src[g_eord[j]];
        float w = aE[j];
        const float4* row = (const float4*)(h + (size_t)s * D_HID);
        float4 v = row[t];
        a0 += v.x * w;
        a1 += v.y * w;
        a2 += v.z * w;
        a3 += v.w * w;
    }
    const float4 bb = ((const float4*)bias)[t];
    float4 o = {a0 + bb.x, a1 + bb.y, a2 + bb.z, a3 + bb.w};
    ((float4*)(out + (size_t)n * D_HID))[t] = o;
}

// ---------------- launch ----------------------------------------------------
extern "C" void kernel_launch(void* const* d_in, const int* in_sizes, int n_in,
                              void* d_out, int out_size) {
    const float* x      = (const float*)d_in[0];
    const float* W1     = (const float*)d_in[1];
    const float* a_src1 = (const float*)d_in[2];
    const float* a_dst1 = (const float*)d_in[3];
    const float* b1     = (const float*)d_in[4];
    const float* W2     = (const float*)d_in[5];
    const float* a_src2 = (const float*)d_in[6];
    const float* a_dst2 = (const float*)d_in[7];
    const float* b2     = (const float*)d_in[8];
    const int*   el     = (const int*)d_in[9];
    const int* srcA = el;
    const int* dstA = el + N_EDGES;
    float* out = (float*)d_out;

    float *p_h1, *p_h2, *p_as1, *p_ad1, *p_aE1, *p_as2, *p_ad2, *p_aE2;
    __half *p_xf, *p_w1h, *p_w1l, *p_w2h, *p_w2l, *p_o1f;
    cudaGetSymbolAddress((void**)&p_h1,  g_h1);
    cudaGetSymbolAddress((void**)&p_h2,  g_h2);
    cudaGetSymbolAddress((void**)&p_xf,  g_xf);
    cudaGetSymbolAddress((void**)&p_w1h, g_w1h);
    cudaGetSymbolAddress((void**)&p_w1l, g_w1l);
    cudaGetSymbolAddress((void**)&p_w2h, g_w2h);
    cudaGetSymbolAddress((void**)&p_w2l, g_w2l);
    cudaGetSymbolAddress((void**)&p_o1f, g_o1f);
    cudaGetSymbolAddress((void**)&p_as1, g_as1);
    cudaGetSymbolAddress((void**)&p_ad1, g_ad1);
    cudaGetSymbolAddress((void**)&p_aE1, g_aE1);
    cudaGetSymbolAddress((void**)&p_as2, g_as2);
    cudaGetSymbolAddress((void**)&p_ad2, g_ad2);
    cudaGetSymbolAddress((void**)&p_aE2, g_aE2);

    static bool s_attr_done = false;
    if (!s_attr_done) {
        cudaFuncSetAttribute(k_mma_gemm, cudaFuncAttributeMaxDynamicSharedMemorySize,
                             2 * STG_HALFS * 2);
        s_attr_done = true;
    }
    const int smem_bytes = 2 * STG_HALFS * 2;  // 55296

    // CSR build
    k_zero_cnt<<<N_NODES / 256, 256>>>();
    k_count<<<N_EDGES / 256, 256>>>(dstA);
    k_scan<<<1, 1024>>>();
    k_scatter<<<N_EDGES / 256, 256>>>(dstA);

    // operand prep
    k_round4<<<(N_NODES * D_IN / 4 + 255) / 256, 256>>>(
        (const float4*)x, (uint2*)p_xf, N_NODES * D_IN / 4);
    k_split4<<<(D_IN * D1 / 4 + 255) / 256, 256>>>(
        (const float4*)W1, (uint2*)p_w1h, (uint2*)p_w1l, D_IN * D1 / 4);
    k_split4<<<(D1 * D_HID / 4 + 255) / 256, 256>>>(
        (const float4*)W2, (uint2*)p_w2h, (uint2*)p_w2l, D1 * D_HID / 4);

    // Layer 1: h1 = x @ W1
    dim3 g1(D1 / 128, N_NODES / 128);
    k_mma_gemm<<<g1, 256, smem_bytes>>>(p_xf, p_w1h, p_w1l, p_h1, N_NODES, D1, D_IN);
    k_attn<<<N_NODES, 32 * H1>>>(p_h1, a_src1, a_dst1, p_as1, p_ad1, H1);
    k_softmax<<<N_NODES, 32 * H1>>>(srcA, p_as1, p_ad1, p_aE1, H1);
    dim3 ga1(N_NODES, H1);
    k_aggregate_l1<<<ga1, 192>>>(srcA, p_h1, p_aE1, b1, p_o1f);

    // Layer 2: h2 = out1 @ W2
    dim3 g2(D_HID / 128, N_NODES / 128);
    k_mma_gemm<<<g2, 256, smem_bytes>>>(p_o1f, p_w2h, p_w2l, p_h2, N_NODES, D_HID, D1);
    k_attn<<<N_NODES, 32>>>(p_h2, a_src2, a_dst2, p_as2, p_ad2, 1);
    k_softmax<<<N_NODES, 32>>>(srcA, p_as2, p_ad2, p_aE2, 1);
    k_aggregate_l2<<<N_NODES, 192>>>(srcA, p_h2, p_aE2, b2, out);
}

// round 5
// speedup vs baseline: 4.2265x; 1.0252x over previous
#include <cuda_runtime.h>
#include <cuda_fp16.h>
#include <cstdint>

#define N_NODES 8192
#define N_EDGES 65536
#define D_IN    768
#define D_HID   768
#define H1      8
#define D1      (H1 * D_HID)   // 6144

// ---------------- scratch (static device globals) ---------------------------
__device__ __half g_h1f[(size_t)N_NODES * D1];    // fp16 x@W1
__device__ float  g_h2[(size_t)N_NODES * D_HID];  // fp32 out1@W2 (atomic accum)
__device__ __half g_xf[(size_t)N_NODES * D_IN];   // fp16(x)
__device__ __half g_w1h[(size_t)D_IN * D1];
__device__ __half g_w1l[(size_t)D_IN * D1];
__device__ __half g_w2h[(size_t)D1 * D_HID];
__device__ __half g_w2l[(size_t)D1 * D_HID];
__device__ __half g_o1f[(size_t)N_NODES * D1];    // fp16(out1)
__device__ float  g_as1[N_NODES * H1];
__device__ float  g_ad1[N_NODES * H1];
__device__ float  g_aE1[(size_t)N_EDGES * H1];
__device__ float  g_as2[N_NODES];
__device__ float  g_ad2[N_NODES];
__device__ float  g_aE2[N_EDGES];
__device__ int    g_cnt[N_NODES];
__device__ int    g_indptr[N_NODES + 1];
__device__ int    g_cur[N_NODES];
__device__ int    g_eord[N_EDGES];

// ---------------- utility kernels -------------------------------------------
__global__ void k_zero_f(float* __restrict__ p, int n) {
    int i = blockIdx.x * blockDim.x + threadIdx.x;
    if (i < n) p[i] = 0.f;
}

// ---------------- CSR build ------------------------------------------------
__global__ void k_zero_cnt() {
    int i = blockIdx.x * blockDim.x + threadIdx.x;
    if (i < N_NODES) g_cnt[i] = 0;
}
__global__ void k_count(const int* __restrict__ dst) {
    int e = blockIdx.x * blockDim.x + threadIdx.x;
    if (e < N_EDGES) atomicAdd(&g_cnt[dst[e]], 1);
}
__global__ void k_scan() {
    __shared__ int sh[1024];
    int t = threadIdx.x;
    int base = t * 8;
    int local[8];
    int s = 0;
#pragma unroll
    for (int i = 0; i < 8; i++) { local[i] = s; s += g_cnt[base + i]; }
    sh[t] = s;
    __syncthreads();
    for (int off = 1; off < 1024; off <<= 1) {
        int v = (t >= off) ? sh[t - off] : 0;
        __syncthreads();
        sh[t] += v;
        __syncthreads();
    }
    int prefix = (t == 0) ? 0 : sh[t - 1];
#pragma unroll
    for (int i = 0; i < 8; i++) {
        int v = prefix + local[i];
        g_indptr[base + i] = v;
        g_cur[base + i] = v;
    }
    if (t == 1023) g_indptr[N_NODES] = sh[1023];
}
__global__ void k_scatter(const int* __restrict__ dst) {
    int e = blockIdx.x * blockDim.x + threadIdx.x;
    if (e < N_EDGES) {
        int d = dst[e];
        int p = atomicAdd(&g_cur[d], 1);
        g_eord[p] = e;
    }
}

// ---------------- fp32 -> fp16 round / split ---------------------------------
__global__ void k_round4(const float4* __restrict__ in, uint2* __restrict__ o, int n4) {
    int i = blockIdx.x * blockDim.x + threadIdx.x;
    if (i >= n4) return;
    float4 v = in[i];
    __half2 lo = __floats2half2_rn(v.x, v.y);
    __half2 hi = __floats2half2_rn(v.z, v.w);
    uint2 r;
    r.x = *(uint32_t*)&lo;
    r.y = *(uint32_t*)&hi;
    o[i] = r;
}
__global__ void k_split4(const float4* __restrict__ in,
                         uint2* __restrict__ hi, uint2* __restrict__ lo, int n4) {
    int i = blockIdx.x * blockDim.x + threadIdx.x;
    if (i >= n4) return;
    float4 v = in[i];
    __half hx = __float2half_rn(v.x), hy = __float2half_rn(v.y);
    __half hz = __float2half_rn(v.z), hw = __float2half_rn(v.w);
    __half lx = __float2half_rn(v.x - __half2float(hx));
    __half ly = __float2half_rn(v.y - __half2float(hy));
    __half lz = __float2half_rn(v.z - __half2float(hz));
    __half lw = __float2half_rn(v.w - __half2float(hw));
    uint2 hv, lv;
    hv.x = ((uint32_t)__half_as_ushort(hy) << 16) | __half_as_ushort(hx);
    hv.y = ((uint32_t)__half_as_ushort(hw) << 16) | __half_as_ushort(hz);
    lv.x = ((uint32_t)__half_as_ushort(ly) << 16) | __half_as_ushort(lx);
    lv.y = ((uint32_t)__half_as_ushort(lw) << 16) | __half_as_ushort(lz);
    hi[i] = hv;
    lo[i] = lv;
}

// ---------------- tensor-core GEMM core (2x fp16 product) --------------------
#define A_PAD 40
#define B_PAD 136
#define A_HALFS (128 * A_PAD)
#define B_HALFS (32 * B_PAD)
#define STG_HALFS (A_HALFS + 2 * B_HALFS)  // 13824

#define LDSM4(R, addr) \
    asm volatile("ldmatrix.sync.aligned.m8n8.x4.shared.b16 {%0,%1,%2,%3}, [%4];" \
        : "=r"(R[0]), "=r"(R[1]), "=r"(R[2]), "=r"(R[3]) : "r"(addr))

#define LDSM4T(R0, R1, R2, R3, addr) \
    asm volatile("ldmatrix.sync.aligned.m8n8.x4.trans.shared.b16 {%0,%1,%2,%3}, [%4];" \
        : "=r"(R0), "=r"(R1), "=r"(R2), "=r"(R3) : "r"(addr))

#define MMA16816(D, A, B) \
    asm volatile("mma.sync.aligned.m16n8k16.row.col.f32.f16.f16.f32 " \
        "{%0,%1,%2,%3}, {%4,%5,%6,%7}, {%8,%9}, {%0,%1,%2,%3};" \
        : "+f"(D[0]), "+f"(D[1]), "+f"(D[2]), "+f"(D[3]) \
        : "r"(A[0]), "r"(A[1]), "r"(A[2]), "r"(A[3]), "r"(B[0]), "r"(B[1]))

__device__ __forceinline__ void cp16(uint32_t saddr, const void* g) {
    asm volatile("cp.async.cg.shared.global [%0], [%1], 16;" :: "r"(saddr), "l"(g));
}

// Mainloop as a macro so two kernels share it. Defines c[2][8][4] accumulators.
#define GEMM_MAINLOOP(Af, Bh, Bl, Kdim, NKT)                                        \
    extern __shared__ __half smem[];                                               \
    const uint32_t sbase = (uint32_t)__cvta_generic_to_shared(smem);                \
    const int tid = threadIdx.x;                                                    \
    const int lane = tid & 31;                                                      \
    const int wid = tid >> 5;                                                       \
    const int wm = (wid & 3) * 32;                                                  \
    const int wn = (wid >> 2) * 64;                                                 \
    const int bm = blockIdx.y * 128;                                                \
    const int bn = blockIdx.x * 128;                                                \
    const int arow0 = tid >> 2, acol0 = (tid & 3) * 8;                              \
    const int arow1 = (tid + 256) >> 2, acol1 = ((tid + 256) & 3) * 8;              \
    const int brow0 = tid >> 4, bcol0 = (tid & 15) * 8;                             \
    const int brow1 = (tid + 256) >> 4, bcol1 = ((tid + 256) & 15) * 8;             \
    float c[2][8][4];                                                               \
    _Pragma("unroll") for (int mi = 0; mi < 2; mi++)                                \
        _Pragma("unroll") for (int nj = 0; nj < 8; nj++)                            \
            _Pragma("unroll") for (int q = 0; q < 4; q++) c[mi][nj][q] = 0.f;       \
    auto load_stage = [&](int stage, int kt) {                                      \
        uint32_t aF = sbase + stage * STG_HALFS * 2;                                \
        uint32_t bHs = aF + A_HALFS * 2;                                            \
        uint32_t bLs = bHs + B_HALFS * 2;                                           \
        size_t ga0 = (size_t)(bm + arow0) * (Kdim) + kt + acol0;                    \
        size_t ga1 = (size_t)(bm + arow1) * (Kdim) + kt + acol1;                    \
        cp16(aF + (arow0 * A_PAD + acol0) * 2, (Af) + ga0);                         \
        cp16(aF + (arow1 * A_PAD + acol1) * 2, (Af) + ga1);                         \
        size_t gb0 = (size_t)(kt + brow0) * N + bn + bcol0;                         \
        size_t gb1 = (size_t)(kt + brow1) * N + bn + bcol1;                         \
        uint32_t sb0 = (brow0 * B_PAD + bcol0) * 2;                                 \
        uint32_t sb1 = (brow1 * B_PAD + bcol1) * 2;                                 \
        cp16(bHs + sb0, (Bh) + gb0);                                                \
        cp16(bHs + sb1, (Bh) + gb1);                                                \
        cp16(bLs + sb0, (Bl) + gb0);                                                \
        cp16(bLs + sb1, (Bl) + gb1);                                                \
        asm volatile("cp.async.commit_group;");                                     \
    };                                                                              \
    load_stage(0, 0);                                                               \
    for (int it = 0; it < (NKT); it++) {                                            \
        int stage = it & 1;                                                         \
        if (it + 1 < (NKT)) {                                                       \
            load_stage(stage ^ 1, (it + 1) * 32);                                   \
            asm volatile("cp.async.wait_group 1;");                                 \
        } else {                                                                    \
            asm volatile("cp.async.wait_group 0;");                                 \
        }                                                                           \
        __syncthreads();                                                            \
        uint32_t aF = sbase + stage * STG_HALFS * 2;                                \
        uint32_t bHs = aF + A_HALFS * 2;                                            \
        uint32_t bLs = bHs + B_HALFS * 2;                                           \
        _Pragma("unroll")                                                           \
        for (int ks = 0; ks < 32; ks += 16) {                                       \
            uint32_t af[2][4];                                                      \
            _Pragma("unroll") for (int mi = 0; mi < 2; mi++) {                      \
                uint32_t off = ((wm + mi * 16 + (lane & 15)) * A_PAD + ks +         \
                                (lane >> 4) * 8) * 2;                               \
                LDSM4(af[mi], aF + off);                                            \
            }                                                                       \
            uint32_t bfh[8][2], bfl[8][2];                                          \
            int gq = lane >> 3;                                                     \
            int brow = ks + (lane & 7) + (gq & 1) * 8;                              \
            int bcol_base = wn + (gq >> 1) * 8;                                     \
            _Pragma("unroll") for (int nj2 = 0; nj2 < 4; nj2++) {                   \
                uint32_t off = (brow * B_PAD + bcol_base + nj2 * 16) * 2;           \
                LDSM4T(bfh[nj2 * 2][0], bfh[nj2 * 2][1],                            \
                       bfh[nj2 * 2 + 1][0], bfh[nj2 * 2 + 1][1], bHs + off);        \
                LDSM4T(bfl[nj2 * 2][0], bfl[nj2 * 2][1],                            \
                       bfl[nj2 * 2 + 1][0], bfl[nj2 * 2 + 1][1], bLs + off);        \
            }                                                                       \
            _Pragma("unroll") for (int mi = 0; mi < 2; mi++)                        \
                _Pragma("unroll") for (int nj = 0; nj < 8; nj++) {                  \
                    MMA16816(c[mi][nj], af[mi], bfh[nj]);                           \
                    MMA16816(c[mi][nj], af[mi], bfl[nj]);                           \
                }                                                                   \
        }                                                                           \
        __syncthreads();                                                            \
    }

// Epilogue attention partial dots (exact fp32) + atomicAdd into as/ad.
#define GEMM_ATTN_EPILOGUE(asArr, adArr, aSvec, aDvec, Hn, headIdx)                 \
    {                                                                               \
        float ds[4] = {0.f, 0.f, 0.f, 0.f}, dd[4] = {0.f, 0.f, 0.f, 0.f};           \
        _Pragma("unroll") for (int mi = 0; mi < 2; mi++)                            \
            _Pragma("unroll") for (int nj = 0; nj < 8; nj++) {                      \
                int col = bn + wn + nj * 8 + (lane & 3) * 2;                        \
                float s0 = (aSvec)[col], s1 = (aSvec)[col + 1];                     \
                float d0 = (aDvec)[col], d1 = (aDvec)[col + 1];                     \
                ds[mi * 2 + 0] += c[mi][nj][0] * s0 + c[mi][nj][1] * s1;            \
                ds[mi * 2 + 1] += c[mi][nj][2] * s0 + c[mi][nj][3] * s1;            \
                dd[mi * 2 + 0] += c[mi][nj][0] * d0 + c[mi][nj][1] * d1;            \
                dd[mi * 2 + 1] += c[mi][nj][2] * d0 + c[mi][nj][3] * d1;            \
            }                                                                       \
        _Pragma("unroll") for (int r = 0; r < 4; r++) {                             \
            ds[r] += __shfl_xor_sync(0xffffffffu, ds[r], 1);                        \
            ds[r] += __shfl_xor_sync(0xffffffffu, ds[r], 2);                        \
            dd[r] += __shfl_xor_sync(0xffffffffu, dd[r], 1);                        \
            dd[r] += __shfl_xor_sync(0xffffffffu, dd[r], 2);                        \
        }                                                                           \
        if ((lane & 3) == 0) {                                                      \
            _Pragma("unroll") for (int mi = 0; mi < 2; mi++) {                      \
                int ra = bm + wm + mi * 16 + (lane >> 2);                           \
                atomicAdd(&(asArr)[(size_t)ra * (Hn) + (headIdx)], ds[mi * 2 + 0]); \
                atomicAdd(&(asArr)[(size_t)(ra + 8) * (Hn) + (headIdx)], ds[mi * 2 + 1]); \
                atomicAdd(&(adArr)[(size_t)ra * (Hn) + (headIdx)], dd[mi * 2 + 0]); \
                atomicAdd(&(adArr)[(size_t)(ra + 8) * (Hn) + (headIdx)], dd[mi * 2 + 1]); \
            }                                                                       \
        }                                                                           \
    }

// GEMM1: C fp16 direct store + attention dots for H1 heads.
__global__ __launch_bounds__(256) void k_gemm1(
    const __half* __restrict__ Af,
    const __half* __restrict__ Bh, const __half* __restrict__ Bl,
    __half* __restrict__ Cf, float* __restrict__ asArr, float* __restrict__ adArr,
    const float* __restrict__ aSvec, const float* __restrict__ aDvec,
    int N, int K) {
    GEMM_MAINLOOP(Af, Bh, Bl, K, K / 32)

    const int head = bn / D_HID;
    GEMM_ATTN_EPILOGUE(asArr, adArr, aSvec, aDvec, H1, head)

#pragma unroll
    for (int mi = 0; mi < 2; mi++) {
        int row0 = bm + wm + mi * 16 + (lane >> 2);
#pragma unroll
        for (int nj = 0; nj < 8; nj++) {
            int col = bn + wn + nj * 8 + (lane & 3) * 2;
            __half2 p0 = __floats2half2_rn(c[mi][nj][0], c[mi][nj][1]);
            __half2 p1 = __floats2half2_rn(c[mi][nj][2], c[mi][nj][3]);
            *(__half2*)(Cf + (size_t)row0 * N + col) = p0;
            *(__half2*)(Cf + (size_t)(row0 + 8) * N + col) = p1;
        }
    }
}

// GEMM2: split-K over blockIdx.z, fp32 atomicAdd epilogue + attention dots (H=1).
__global__ __launch_bounds__(256) void k_gemm2(
    const __half* __restrict__ Afull,
    const __half* __restrict__ Bhfull, const __half* __restrict__ Blfull,
    float* __restrict__ C, float* __restrict__ asArr, float* __restrict__ adArr,
    const float* __restrict__ aSvec, const float* __restrict__ aDvec,
    int N, int Kfull, int ksplit) {
    const int kpart = Kfull / ksplit;
    const int kbase = blockIdx.z * kpart;
    const __half* Af = Afull + kbase;            // row stride remains Kfull
    const __half* Bh = Bhfull + (size_t)kbase * N;
    const __half* Bl = Blfull + (size_t)kbase * N;

    GEMM_MAINLOOP(Af, Bh, Bl, Kfull, kpart / 32)

    GEMM_ATTN_EPILOGUE(asArr, adArr, aSvec, aDvec, 1, 0)

#pragma unroll
    for (int mi = 0; mi < 2; mi++) {
        int row0 = bm + wm + mi * 16 + (lane >> 2);
#pragma unroll
        for (int nj = 0; nj < 8; nj++) {
            int col = bn + wn + nj * 8 + (lane & 3) * 2;
            float* p0 = C + (size_t)row0 * N + col;
            float* p1 = C + (size_t)(row0 + 8) * N + col;
            atomicAdd(p0, c[mi][nj][0]);
            atomicAdd(p0 + 1, c[mi][nj][1]);
            atomicAdd(p1, c[mi][nj][2]);
            atomicAdd(p1 + 1, c[mi][nj][3]);
        }
    }
}

// ---------------- segment softmax over CSR -----------------------------------
__global__ void k_softmax(const int* __restrict__ src,
                          const float* __restrict__ as,
                          const float* __restrict__ ad,
                          float* __restrict__ aE, int H) {
    int n = blockIdx.x;
    int hh = threadIdx.x >> 5;
    int lane = threadIdx.x & 31;
    int beg = g_indptr[n], end = g_indptr[n + 1];
    if (beg == end) return;
    float adn = ad[(size_t)n * H + hh];

    float m = -3.4e38f;
    for (int j = beg + lane; j < end; j += 32) {
        int s = src[g_eord[j]];
        float v = as[(size_t)s * H + hh] + adn;
        v = v > 0.f ? v : 0.2f * v;
        m = fmaxf(m, v);
    }
#pragma unroll
    for (int o = 16; o; o >>= 1) m = fmaxf(m, __shfl_xor_sync(0xffffffffu, m, o));

    float sum = 0.f;
    for (int j = beg + lane; j < end; j += 32) {
        int s = src[g_eord[j]];
        float v = as[(size_t)s * H + hh] + adn;
        v = v > 0.f ? v : 0.2f * v;
        float ex = __expf(v - m);
        aE[(size_t)j * H + hh] = ex;
        sum += ex;
    }
#pragma unroll
    for (int o = 16; o; o >>= 1) sum += __shfl_xor_sync(0xffffffffu, sum, o);

    float inv = 1.f / (sum + 1e-16f);
    for (int j = beg + lane; j < end; j += 32)
        aE[(size_t)j * H + hh] *= inv;
}

// ---------------- aggregation layer 1: fp16 gather -> fp16 out ---------------
__global__ __launch_bounds__(192) void k_aggregate_l1(const int* __restrict__ src,
                                                      const __half* __restrict__ hf,
                                                      const float* __restrict__ aE,
                                                      const float* __restrict__ bias,
                                                      __half* __restrict__ of) {
    int n = blockIdx.x;
    int hh = blockIdx.y;
    int t = threadIdx.x;
    int beg = g_indptr[n], end = g_indptr[n + 1];

    float a0 = 0.f, a1 = 0.f, a2 = 0.f, a3 = 0.f;
    for (int j = beg; j < end; j++) {
        int s = src[g_eord[j]];
        float w = aE[(size_t)j * H1 + hh];
        uint2 rv = *(const uint2*)(hf + ((size_t)s * H1 + hh) * D_HID + t * 4);
        __half2 h01 = *(__half2*)&rv.x;
        __half2 h23 = *(__half2*)&rv.y;
        float2 f01 = __half22float2(h01);
        float2 f23 = __half22float2(h23);
        a0 += f01.x * w;
        a1 += f01.y * w;
        a2 += f23.x * w;
        a3 += f23.y * w;
    }
    const float4 bb = *(const float4*)(bias + (size_t)hh * D_HID + t * 4);
    float v0 = a0 + bb.x;
    float v1 = a1 + bb.y;
    float v2 = a2 + bb.z;
    float v3 = a3 + bb.w;
    v0 = v0 > 0.f ? v0 : (__expf(v0) - 1.f);
    v1 = v1 > 0.f ? v1 : (__expf(v1) - 1.f);
    v2 = v2 > 0.f ? v2 : (__expf(v2) - 1.f);
    v3 = v3 > 0.f ? v3 : (__expf(v3) - 1.f);
    __half2 lo = __floats2half2_rn(v0, v1);
    __half2 hi = __floats2half2_rn(v2, v3);
    uint2 r;
    r.x = *(uint32_t*)&lo;
    r.y = *(uint32_t*)&hi;
    *(uint2*)(of + ((size_t)n * H1 + hh) * D_HID + t * 4) = r;
}

// ---------------- aggregation layer 2: fp32, no ELU ---------------------------
__global__ __launch_bounds__(192) void k_aggregate_l2(const int* __restrict__ src,
                                                      const float* __restrict__ h,
                                                      const float* __restrict__ aE,
                                                      const float* __restrict__ bias,
                                                      float* __restrict__ out) {
    int n = blockIdx.x;
    int t = threadIdx.x;
    int beg = g_indptr[n], end = g_indptr[n + 1];

    float a0 = 0.f, a1 = 0.f, a2 = 0.f, a3 = 0.f;
    for (int j = beg; j < end; j++) {
        int s = src[g_eord[j]];
        float w = aE[j];
        float4 v = *(const float4*)(h + (size_t)s * D_HID + t * 4);
        a0 += v.x * w;
        a1 += v.y * w;
        a2 += v.z * w;
        a3 += v.w * w;
    }
    const float4 bb = *(const float4*)(bias + t * 4);
    float4 o = {a0 + bb.x, a1 + bb.y, a2 + bb.z, a3 + bb.w};
    *(float4*)(out + (size_t)n * D_HID + t * 4) = o;
}

// ---------------- launch ----------------------------------------------------
extern "C" void kernel_launch(void* const* d_in, const int* in_sizes, int n_in,
                              void* d_out, int out_size) {
    const float* x      = (const float*)d_in[0];
    const float* W1     = (const float*)d_in[1];
    const float* a_src1 = (const float*)d_in[2];
    const float* a_dst1 = (const float*)d_in[3];
    const float* b1     = (const float*)d_in[4];
    const float* W2     = (const float*)d_in[5];
    const float* a_src2 = (const float*)d_in[6];
    const float* a_dst2 = (const float*)d_in[7];
    const float* b2     = (const float*)d_in[8];
    const int*   el     = (const int*)d_in[9];
    const int* srcA = el;
    const int* dstA = el + N_EDGES;
    float* out = (float*)d_out;

    float *p_h2, *p_as1, *p_ad1, *p_aE1, *p_as2, *p_ad2, *p_aE2;
    __half *p_h1f, *p_xf, *p_w1h, *p_w1l, *p_w2h, *p_w2l, *p_o1f;
    cudaGetSymbolAddress((void**)&p_h1f, g_h1f);
    cudaGetSymbolAddress((void**)&p_h2,  g_h2);
    cudaGetSymbolAddress((void**)&p_xf,  g_xf);
    cudaGetSymbolAddress((void**)&p_w1h, g_w1h);
    cudaGetSymbolAddress((void**)&p_w1l, g_w1l);
    cudaGetSymbolAddress((void**)&p_w2h, g_w2h);
    cudaGetSymbolAddress((void**)&p_w2l, g_w2l);
    cudaGetSymbolAddress((void**)&p_o1f, g_o1f);
    cudaGetSymbolAddress((void**)&p_as1, g_as1);
    cudaGetSymbolAddress((void**)&p_ad1, g_ad1);
    cudaGetSymbolAddress((void**)&p_aE1, g_aE1);
    cudaGetSymbolAddress((void**)&p_as2, g_as2);
    cudaGetSymbolAddress((void**)&p_ad2, g_ad2);
    cudaGetSymbolAddress((void**)&p_aE2, g_aE2);

    static bool s_attr_done = false;
    if (!s_attr_done) {
        cudaFuncSetAttribute(k_gemm1, cudaFuncAttributeMaxDynamicSharedMemorySize,
                             2 * STG_HALFS * 2);
        cudaFuncSetAttribute(k_gemm2, cudaFuncAttributeMaxDynamicSharedMemorySize,
                             2 * STG_HALFS * 2);
        s_attr_done = true;
    }
    const int smem_bytes = 2 * STG_HALFS * 2;  // 55296

    // CSR build
    k_zero_cnt<<<N_NODES / 256, 256>>>();
    k_count<<<N_EDGES / 256, 256>>>(dstA);
    k_scan<<<1, 1024>>>();
    k_scatter<<<N_EDGES / 256, 256>>>(dstA);

    // zero accumulators (re-zeroed every launch; graph-replay safe)
    k_zero_f<<<(N_NODES * H1 + 255) / 256, 256>>>(p_as1, N_NODES * H1);
    k_zero_f<<<(N_NODES * H1 + 255) / 256, 256>>>(p_ad1, N_NODES * H1);
    k_zero_f<<<(N_NODES + 255) / 256, 256>>>(p_as2, N_NODES);
    k_zero_f<<<(N_NODES + 255) / 256, 256>>>(p_ad2, N_NODES);
    k_zero_f<<<(N_NODES * D_HID + 255) / 256, 256>>>(p_h2, N_NODES * D_HID);

    // operand prep
    k_round4<<<(N_NODES * D_IN / 4 + 255) / 256, 256>>>(
        (const float4*)x, (uint2*)p_xf, N_NODES * D_IN / 4);
    k_split4<<<(D_IN * D1 / 4 + 255) / 256, 256>>>(
        (const float4*)W1, (uint2*)p_w1h, (uint2*)p_w1l, D_IN * D1 / 4);
    k_split4<<<(D1 * D_HID / 4 + 255) / 256, 256>>>(
        (const float4*)W2, (uint2*)p_w2h, (uint2*)p_w2l, D1 * D_HID / 4);

    // Layer 1: h1f = fp16(x @ W1), attention dots fused into epilogue
    dim3 g1(D1 / 128, N_NODES / 128);
    k_gemm1<<<g1, 256, smem_bytes>>>(p_xf, p_w1h, p_w1l, p_h1f,
                                     p_as1, p_ad1, a_src1, a_dst1, D1, D_IN);
    k_softmax<<<N_NODES, 32 * H1>>>(srcA, p_as1, p_ad1, p_aE1, H1);
    dim3 ga1(N_NODES, H1);
    k_aggregate_l1<<<ga1, 192>>>(srcA, p_h1f, p_aE1, b1, p_o1f);

    // Layer 2: h2 = out1 @ W2 (split-K=2, atomic accumulate), attn fused
    dim3 g2(D_HID / 128, N_NODES / 128, 2);
    k_gemm2<<<g2, 256, smem_bytes>>>(p_o1f, p_w2h, p_w2l, p_h2,
                                     p_as2, p_ad2, a_src2, a_dst2, D_HID, D1, 2);
    k_softmax<<<N_NODES, 32>>>(srcA, p_as2, p_ad2, p_aE2, 1);
    k_aggregate_l2<<<N_NODES, 192>>>(srcA, p_h2, p_aE2, b2, out);
}